// round 10
// baseline (speedup 1.0000x reference)
#include <cuda_runtime.h>
#include <cuda_bf16.h>
#include <cuda_fp16.h>
#include <cstdint>

#define BATCH 8
#define DM 256
#define NH 4
#define HD 64
#define SEQ 2048
#define BH (BATCH*NH)

typedef unsigned short u16;

// Q: [bh][n][d] fp16 hi/lo (pre-scaled by 0.125*log2e) ; K: [bh][m][d] fp16 ; V: [bh][d][m] fp16
__device__ u16  g_qh[(size_t)BH*SEQ*HD];
__device__ u16  g_ql[(size_t)BH*SEQ*HD];
__device__ u16  g_kh[(size_t)BH*SEQ*HD];
__device__ u16  g_vh[(size_t)BH*HD*SEQ];
__device__ float g_x [(size_t)BATCH*DM*SEQ];

#define QSCALE 0.18033688011112042f   // 0.125 * log2(e)

__device__ __forceinline__ float ex2f(float x) {
    float r; asm("ex2.approx.f32 %0, %1;" : "=f"(r) : "f"(x)); return r;
}
__device__ __forceinline__ uint32_t packh2(float lo, float hi) {
    uint32_t r; asm("cvt.rn.f16x2.f32 %0, %1, %2;" : "=r"(r) : "f"(hi), "f"(lo)); return r;
}
__device__ __forceinline__ void split2(float v0, float v1, uint32_t& hp, uint32_t& lp) {
    asm("cvt.rn.bf16x2.f32 %0, %1, %2;" : "=r"(hp) : "f"(v1), "f"(v0));
    float f0 = __uint_as_float(hp << 16);
    float f1 = __uint_as_float(hp & 0xffff0000u);
    asm("cvt.rn.bf16x2.f32 %0, %1, %2;" : "=r"(lp) : "f"(v1 - f1), "f"(v0 - f0));
}
__device__ __forceinline__ void splithalf(float v, u16& h, u16& l) {
    __half hb = __float2half_rn(v);
    __half lb = __float2half_rn(v - __half2float(hb));
    h = __half_as_ushort(hb); l = __half_as_ushort(lb);
}
__device__ __forceinline__ void mma16816(float* d, const uint32_t* a, uint32_t b0, uint32_t b1) {
    asm volatile("mma.sync.aligned.m16n8k16.row.col.f32.bf16.bf16.f32 "
                 "{%0,%1,%2,%3}, {%4,%5,%6,%7}, {%8,%9}, {%0,%1,%2,%3};\n"
                 : "+f"(d[0]), "+f"(d[1]), "+f"(d[2]), "+f"(d[3])
                 : "r"(a[0]), "r"(a[1]), "r"(a[2]), "r"(a[3]), "r"(b0), "r"(b1));
}
__device__ __forceinline__ void mma16816h(float* d, const uint32_t* a, uint32_t b0, uint32_t b1) {
    asm volatile("mma.sync.aligned.m16n8k16.row.col.f32.f16.f16.f32 "
                 "{%0,%1,%2,%3}, {%4,%5,%6,%7}, {%8,%9}, {%0,%1,%2,%3};\n"
                 : "+f"(d[0]), "+f"(d[1]), "+f"(d[2]), "+f"(d[3])
                 : "r"(a[0]), "r"(a[1]), "r"(a[2]), "r"(a[3]), "r"(b0), "r"(b1));
}
__device__ __forceinline__ void ldsm4(uint32_t a, uint32_t& r0, uint32_t& r1,
                                      uint32_t& r2, uint32_t& r3) {
    asm volatile("ldmatrix.sync.aligned.m8n8.x4.shared.b16 {%0,%1,%2,%3}, [%4];"
                 : "=r"(r0), "=r"(r1), "=r"(r2), "=r"(r3) : "r"(a));
}
__device__ __forceinline__ void ldsm4t(uint32_t a, uint32_t& r0, uint32_t& r1,
                                       uint32_t& r2, uint32_t& r3) {
    asm volatile("ldmatrix.sync.aligned.m8n8.x4.trans.shared.b16 {%0,%1,%2,%3}, [%4];"
                 : "=r"(r0), "=r"(r1), "=r"(r2), "=r"(r3) : "r"(a));
}
__device__ __forceinline__ void cp16(uint32_t saddr, const void* g) {
    asm volatile("cp.async.ca.shared.global [%0], [%1], 16;" :: "r"(saddr), "l"(g));
}
#define CP_COMMIT() asm volatile("cp.async.commit_group;" ::: "memory")
#define CP_WAIT(n)  asm volatile("cp.async.wait_group %0;" :: "n"(n) : "memory")

// ---------------------------------------------------------------------------
// Tensor-core projection (bf16 3-term, term-major MMA ordering).
// K chunk = 64 (4 chunks, 8 syncthreads). Dynamic smem 52KB, 2 CTAs/SM.
// MODE 0: fp32 [b][o][n]; MODE 1: fp16 hi/lo [bh][n][d], pre-scaled (Q);
// MODE 3: fp16 hi [bh][n][d] (K); MODE 2: fp16 hi [bh][d][m] (V).
// Grid (SEQ/64, DM/128, BATCH). 256 threads.
// ---------------------------------------------------------------------------
#define PWH 0
#define PWL 17408
#define PXH 34816
#define PXL 44032
#define PSM_BYTES 53248

template<int MODE>
__global__ __launch_bounds__(256, 2)
void proj_tc(const float* __restrict__ W, const float* __restrict__ bias,
             const float* __restrict__ X, float* __restrict__ C0,
             u16* __restrict__ Ch, u16* __restrict__ Cl) {
    extern __shared__ __align__(16) char psm[];
    __shared__ float biasSm[128];
    const uint32_t sbase = (uint32_t)__cvta_generic_to_shared(psm);
    const int n0 = blockIdx.x * 64, o0 = blockIdx.y * 128, b = blockIdx.z;
    const int tid = threadIdx.x;
    const int w = tid >> 5, l = tid & 31;
    const int g = l >> 2, tt = l & 3;
    if (tid < 128) biasSm[tid] = bias[o0 + tid];

    float O[8][4];
    #pragma unroll
    for (int i = 0; i < 8; i++) { O[i][0]=0.f; O[i][1]=0.f; O[i][2]=0.f; O[i][3]=0.f; }

    const uint32_t xoff = (uint32_t)((8*((l >> 3) & 1) + (l & 7)) * 144 + 16 * (l >> 4));
    const int wo  = tid >> 1, wi0 = (tid & 1) * 32;   // W stage map
    const int xi  = tid >> 2, xn0 = (tid & 3) * 16;   // X stage map

    for (int c = 0; c < 4; c++) {
        const int k0 = c * 64;
        __syncthreads();
        // ---- stage W chunk [128 o][64 i] split hi/lo (pitch 136B)
        #pragma unroll
        for (int p = 0; p < 8; p++) {
            float4 v = *(const float4*)&W[(size_t)(o0 + wo) * DM + k0 + wi0 + 4*p];
            uint32_t h01, l01, h23, l23;
            split2(v.x, v.y, h01, l01);
            split2(v.z, v.w, h23, l23);
            *(uint2*)(psm + PWH + wo*136 + (wi0 + 4*p)*2) = make_uint2(h01, h23);
            *(uint2*)(psm + PWL + wo*136 + (wi0 + 4*p)*2) = make_uint2(l01, l23);
        }
        // ---- stage X chunk [64 i][64 n] split hi/lo (pitch 144B)
        #pragma unroll
        for (int p = 0; p < 4; p++) {
            float4 v = *(const float4*)&X[((size_t)b * DM + k0 + xi) * SEQ + n0 + xn0 + 4*p];
            uint32_t h01, l01, h23, l23;
            split2(v.x, v.y, h01, l01);
            split2(v.z, v.w, h23, l23);
            *(uint2*)(psm + PXH + xi*144 + (xn0 + 4*p)*2) = make_uint2(h01, h23);
            *(uint2*)(psm + PXL + xi*144 + (xn0 + 4*p)*2) = make_uint2(l01, l23);
        }
        __syncthreads();
        // ---- compute: 4 k16 slabs, term-major for ILP
        #pragma unroll
        for (int s = 0; s < 4; s++) {
            uint32_t ah[4], al[4];
            const char* wp = psm + PWH + (w*16 + g)*136 + s*32 + tt*4;
            ah[0] = *(const uint32_t*)wp;
            ah[1] = *(const uint32_t*)(wp + 8*136);
            ah[2] = *(const uint32_t*)(wp + 16);
            ah[3] = *(const uint32_t*)(wp + 8*136 + 16);
            const char* wq = wp + (PWL - PWH);
            al[0] = *(const uint32_t*)wq;
            al[1] = *(const uint32_t*)(wq + 8*136);
            al[2] = *(const uint32_t*)(wq + 16);
            al[3] = *(const uint32_t*)(wq + 8*136 + 16);
            const uint32_t xb = sbase + PXH + s*2304 + xoff;
            uint32_t xh[4][4], xq[4][4];
            #pragma unroll
            for (int nbp = 0; nbp < 4; nbp++) {
                ldsm4t(xb + 32*nbp,               xh[nbp][0], xh[nbp][1], xh[nbp][2], xh[nbp][3]);
                ldsm4t(xb + 32*nbp + (PXL - PXH), xq[nbp][0], xq[nbp][1], xq[nbp][2], xq[nbp][3]);
            }
            #pragma unroll
            for (int nbp = 0; nbp < 4; nbp++) {
                mma16816(O[2*nbp],   ah, xh[nbp][0], xh[nbp][1]);
                mma16816(O[2*nbp+1], ah, xh[nbp][2], xh[nbp][3]);
            }
            #pragma unroll
            for (int nbp = 0; nbp < 4; nbp++) {
                mma16816(O[2*nbp],   ah, xq[nbp][0], xq[nbp][1]);
                mma16816(O[2*nbp+1], ah, xq[nbp][2], xq[nbp][3]);
            }
            #pragma unroll
            for (int nbp = 0; nbp < 4; nbp++) {
                mma16816(O[2*nbp],   al, xh[nbp][0], xh[nbp][1]);
                mma16816(O[2*nbp+1], al, xh[nbp][2], xh[nbp][3]);
            }
        }
    }
    __syncthreads();
    float* Osm = (float*)psm;
    {
        const int r = w*16 + g;
        #pragma unroll
        for (int nb = 0; nb < 8; nb++) {
            const int cc = nb*8 + 2*tt;
            Osm[r*68 + cc]         = O[nb][0];
            Osm[r*68 + cc + 1]     = O[nb][1];
            Osm[(r+8)*68 + cc]     = O[nb][2];
            Osm[(r+8)*68 + cc + 1] = O[nb][3];
        }
    }
    __syncthreads();

    if (MODE == 0) {
        const int o = tid >> 1, half = (tid & 1) * 32;
        const float bi = biasSm[o];
        const float* src = Osm + o*68 + half;
        float* dst = C0 + ((size_t)b * DM + o0 + o) * SEQ + n0 + half;
        #pragma unroll
        for (int j = 0; j < 8; j++) {
            float4 v = *(const float4*)(src + 4*j);
            v.x += bi; v.y += bi; v.z += bi; v.w += bi;
            *(float4*)(dst + 4*j) = v;
        }
    } else if (MODE == 1) {
        const int n = tid >> 2, hh = tid & 3;
        u16 oh[32], ol[32];
        #pragma unroll
        for (int d = 0; d < 32; d++)
            splithalf((Osm[(4*d + hh)*68 + n] + biasSm[4*d + hh]) * QSCALE, oh[d], ol[d]);
        size_t dst = ((size_t)(b*NH + hh) * SEQ + n0 + n) * HD + (o0 >> 2);
        #pragma unroll
        for (int j = 0; j < 4; j++) {
            *(uint4*)(Ch + dst + 8*j) = *(uint4*)(oh + 8*j);
            *(uint4*)(Cl + dst + 8*j) = *(uint4*)(ol + 8*j);
        }
    } else if (MODE == 3) {
        const int n = tid >> 2, hh = tid & 3;
        u16 oh[32];
        #pragma unroll
        for (int d = 0; d < 32; d++)
            oh[d] = __half_as_ushort(__float2half_rn(Osm[(4*d + hh)*68 + n] + biasSm[4*d + hh]));
        size_t dst = ((size_t)(b*NH + hh) * SEQ + n0 + n) * HD + (o0 >> 2);
        #pragma unroll
        for (int j = 0; j < 4; j++)
            *(uint4*)(Ch + dst + 8*j) = *(uint4*)(oh + 8*j);
    } else {
        const int ol_ = tid >> 1, mh = (tid & 1) * 32;
        const int chn = o0 + ol_;
        const int d = chn >> 2, hh = chn & 3;
        const float bi = biasSm[ol_];
        const float* src = Osm + ol_*68 + mh;
        u16 xh[32];
        #pragma unroll
        for (int j = 0; j < 32; j++)
            xh[j] = __half_as_ushort(__float2half_rn(src[j] + bi));
        size_t dst = ((size_t)(b*NH + hh) * HD + d) * SEQ + n0 + mh;
        #pragma unroll
        for (int j = 0; j < 4; j++)
            *(uint4*)(Ch + dst + 8*j) = *(uint4*)(xh + 8*j);
    }
}

// ---------------------------------------------------------------------------
// Fused flash attention: fp16, Q 2-term (pre-scaled), K/V/P single-term,
// ls via all-ones MMA, 4-chain S-phase ILP. Double-buffered cp.async. 2 CTAs/SM.
// 256 threads = 8 warps x 16 q-rows. Grid (SEQ/128, BH). smem 106KB.
// ---------------------------------------------------------------------------
#define KPITCH 144
#define VPITCH 272
#define STG 35840            // K (18432) + V (17408) per stage
#define QOFF 71680           // Q hi at QOFF, Q lo at QOFF+18432
#define FLASH_SMEM 108544

__global__ __launch_bounds__(256, 2)
void flash_kernel(const u16* __restrict__ qh, const u16* __restrict__ ql,
                  const u16* __restrict__ kh, const u16* __restrict__ vh,
                  float* __restrict__ X) {
    extern __shared__ __align__(16) char sm[];
    const uint32_t sbase = (uint32_t)__cvta_generic_to_shared(sm);
    const int n0 = blockIdx.x * 128;
    const int bh = blockIdx.y;
    const int b = bh >> 2, h = bh & 3;
    const int t = threadIdx.x;
    const int w = t >> 5, l = t & 31;
    const int g = l >> 2, tt = l & 3;
    const uint32_t ONES = 0x3C003C00u;

    // copy maps
    const int km = t >> 1, khalf = (t & 1) * 32;
    const int vd = t >> 2, vm0 = (t & 3) * 32;
    const uint32_t kso = (uint32_t)(km * KPITCH + khalf * 2);
    const uint32_t vso = (uint32_t)(vd * VPITCH + vm0 * 2);
    const u16* kg = kh + ((size_t)bh*SEQ + km) * HD + khalf;
    const u16* vg = vh + ((size_t)bh*HD + vd) * SEQ + vm0;

    // ldmatrix lane-constant bases
    const uint32_t kfb = (uint32_t)((l & 7) * KPITCH + 16 * (l >> 3));
    const uint32_t vfb = (uint32_t)(((l & 7) + 8*(l >> 4)) * VPITCH + 16 * ((l >> 3) & 1));

    // ---- prologue: Q (hi+lo), then K0/V0, K1/V1
    {
        const u16* qgh = qh + ((size_t)bh*SEQ + n0 + km) * HD + khalf;
        const u16* qgl = ql + ((size_t)bh*SEQ + n0 + km) * HD + khalf;
        #pragma unroll
        for (int u = 0; u < 4; u++) {
            cp16(sbase + QOFF + kso + 16*u,         qgh + 8*u);
            cp16(sbase + QOFF + 18432 + kso + 16*u, qgl + 8*u);
        }
        CP_COMMIT();
        #pragma unroll
        for (int u = 0; u < 4; u++) {
            cp16(sbase + kso + 16*u,         kg + 8*u);
            cp16(sbase + 18432 + vso + 16*u, vg + 8*u);
        }
        CP_COMMIT();
        #pragma unroll
        for (int u = 0; u < 4; u++) {
            cp16(sbase + STG + kso + 16*u,         kg + (size_t)128*HD + 8*u);
            cp16(sbase + STG + 18432 + vso + 16*u, vg + 128 + 8*u);
        }
        CP_COMMIT();
    }
    CP_WAIT(2);
    __syncthreads();
    uint32_t qa_h[4][4], qa_l[4][4];
    {
        const char* QH = sm + QOFF;
        const char* QL = sm + QOFF + 18432;
        const int r0 = (16*w + g) * KPITCH;
        #pragma unroll
        for (int j = 0; j < 4; j++) {
            const int c = (16*j + 2*tt) * 2;
            qa_h[j][0] = *(const uint32_t*)(QH + r0 + c);
            qa_h[j][1] = *(const uint32_t*)(QH + r0 + 8*KPITCH + c);
            qa_h[j][2] = *(const uint32_t*)(QH + r0 + c + 16);
            qa_h[j][3] = *(const uint32_t*)(QH + r0 + 8*KPITCH + c + 16);
            qa_l[j][0] = *(const uint32_t*)(QL + r0 + c);
            qa_l[j][1] = *(const uint32_t*)(QL + r0 + 8*KPITCH + c);
            qa_l[j][2] = *(const uint32_t*)(QL + r0 + c + 16);
            qa_l[j][3] = *(const uint32_t*)(QL + r0 + 8*KPITCH + c + 16);
        }
    }

    float O[8][4];
    #pragma unroll
    for (int i = 0; i < 8; i++) { O[i][0]=0.f; O[i][1]=0.f; O[i][2]=0.f; O[i][3]=0.f; }
    float lsacc[4] = {0.f, 0.f, 0.f, 0.f};
    uint32_t phi[8][2];

    for (int it = 0; it < 16; it++) {
        if (it < 15) { CP_WAIT(1); } else { CP_WAIT(0); }
        __syncthreads();
        const uint32_t kb = sbase + (it & 1) * STG + kfb;
        const uint32_t vb = sbase + (it & 1) * STG + 18432 + vfb;

        #pragma unroll
        for (int half = 0; half < 2; half++) {
            // ---- S = (q_hi + q_lo) * k : 4 chains of depth 2 for ILP
            #pragma unroll
            for (int mc = 0; mc < 8; mc++) {
                float sa0[4] = {0.f,0.f,0.f,0.f};
                float sa1[4] = {0.f,0.f,0.f,0.f};
                float sb0[4] = {0.f,0.f,0.f,0.f};
                float sb1[4] = {0.f,0.f,0.f,0.f};
                const uint32_t rbase = (uint32_t)((64*half + 8*mc) * KPITCH);
                uint32_t bh_[8];
                ldsm4(kb + rbase,      bh_[0], bh_[1], bh_[2], bh_[3]);
                ldsm4(kb + rbase + 64, bh_[4], bh_[5], bh_[6], bh_[7]);
                mma16816h(sa0, qa_h[0], bh_[0], bh_[1]);
                mma16816h(sb0, qa_l[0], bh_[0], bh_[1]);
                mma16816h(sa1, qa_h[1], bh_[2], bh_[3]);
                mma16816h(sb1, qa_l[1], bh_[2], bh_[3]);
                mma16816h(sa0, qa_h[2], bh_[4], bh_[5]);
                mma16816h(sb0, qa_l[2], bh_[4], bh_[5]);
                mma16816h(sa1, qa_h[3], bh_[6], bh_[7]);
                mma16816h(sb1, qa_l[3], bh_[6], bh_[7]);
                float p0 = ex2f((sa0[0] + sa1[0]) + (sb0[0] + sb1[0]));
                float p1 = ex2f((sa0[1] + sa1[1]) + (sb0[1] + sb1[1]));
                float p2 = ex2f((sa0[2] + sa1[2]) + (sb0[2] + sb1[2]));
                float p3 = ex2f((sa0[3] + sa1[3]) + (sb0[3] + sb1[3]));
                phi[mc][0] = packh2(p0, p1);
                phi[mc][1] = packh2(p2, p3);
            }
            // ---- O += P * v ; ls += P * 1  (9 independent chains per jj)
            #pragma unroll
            for (int jj = 0; jj < 4; jj++) {
                uint32_t ah[4] = { phi[2*jj][0], phi[2*jj][1], phi[2*jj+1][0], phi[2*jj+1][1] };
                mma16816h(lsacc, ah, ONES, ONES);
                const uint32_t vcol = (uint32_t)(128*half + 32*jj);
                #pragma unroll
                for (int dcp = 0; dcp < 4; dcp++) {
                    uint32_t h0,h1,h2,h3;
                    ldsm4(vb + dcp*(16*VPITCH) + vcol, h0, h1, h2, h3);
                    mma16816h(O[2*dcp],   ah, h0, h1);
                    mma16816h(O[2*dcp+1], ah, h2, h3);
                }
            }
        }
        __syncthreads();   // all reads of buf[it&1] done
        if (it < 14) {     // stage (it+2) into buf[it&1]
            const u16* pk = kg + (size_t)(it + 2) * 128 * HD;
            const u16* pv = vg + (size_t)(it + 2) * 128;
            const uint32_t dk = sbase + (it & 1) * STG + kso;
            const uint32_t dv = sbase + (it & 1) * STG + 18432 + vso;
            #pragma unroll
            for (int u = 0; u < 4; u++) {
                cp16(dk + 16*u, pk + 8*u);
                cp16(dv + 16*u, pv + 8*u);
            }
            CP_COMMIT();
        }
    }

    const float i0 = 1.f / lsacc[0], i1 = 1.f / lsacc[2];
    #pragma unroll
    for (int dc = 0; dc < 8; dc++) {
        const int d0 = 8*dc + 2*tt;
        float* xp = X + ((size_t)b*DM + 4*d0 + h) * SEQ + n0 + 16*w;
        xp[g]             = O[dc][0] * i0;
        xp[4*SEQ + g]     = O[dc][1] * i0;
        xp[g + 8]         = O[dc][2] * i1;
        xp[4*SEQ + g + 8] = O[dc][3] * i1;
    }
}

// ---------------------------------------------------------------------------
extern "C" void kernel_launch(void* const* d_in, const int* in_sizes, int n_in,
                              void* d_out, int out_size) {
    const float* query = (const float*)d_in[0];
    const float* key   = (const float*)d_in[1];
    const float* value = (const float*)d_in[2];
    const float* Wq = (const float*)d_in[3];
    const float* bq = (const float*)d_in[4];
    const float* Wk = (const float*)d_in[5];
    const float* bk = (const float*)d_in[6];
    const float* Wv = (const float*)d_in[7];
    const float* bv = (const float*)d_in[8];
    const float* Wm = (const float*)d_in[9];
    const float* bm = (const float*)d_in[10];

    u16 *qh, *ql, *kh, *vh;
    float *x;
    cudaGetSymbolAddress((void**)&qh, g_qh);
    cudaGetSymbolAddress((void**)&ql, g_ql);
    cudaGetSymbolAddress((void**)&kh, g_kh);
    cudaGetSymbolAddress((void**)&vh, g_vh);
    cudaGetSymbolAddress((void**)&x,  g_x);

    cudaFuncSetAttribute(flash_kernel, cudaFuncAttributeMaxDynamicSharedMemorySize, FLASH_SMEM);
    cudaFuncSetAttribute(proj_tc<0>, cudaFuncAttributeMaxDynamicSharedMemorySize, PSM_BYTES);
    cudaFuncSetAttribute(proj_tc<1>, cudaFuncAttributeMaxDynamicSharedMemorySize, PSM_BYTES);
    cudaFuncSetAttribute(proj_tc<2>, cudaFuncAttributeMaxDynamicSharedMemorySize, PSM_BYTES);
    cudaFuncSetAttribute(proj_tc<3>, cudaFuncAttributeMaxDynamicSharedMemorySize, PSM_BYTES);

    dim3 pjGrid(SEQ/64, DM/128, BATCH);
    proj_tc<1><<<pjGrid, 256, PSM_BYTES>>>(Wq, bq, query, nullptr, qh, ql);
    proj_tc<3><<<pjGrid, 256, PSM_BYTES>>>(Wk, bk, key,   nullptr, kh, nullptr);
    proj_tc<2><<<pjGrid, 256, PSM_BYTES>>>(Wv, bv, value, nullptr, vh, nullptr);

    flash_kernel<<<dim3(SEQ/128, BH), 256, FLASH_SMEM>>>(qh, ql, kh, vh, x);

    proj_tc<0><<<pjGrid, 256, PSM_BYTES>>>(Wm, bm, x, (float*)d_out, nullptr, nullptr);
}

// round 11
// speedup vs baseline: 1.1279x; 1.1279x over previous
#include <cuda_runtime.h>
#include <cuda_bf16.h>
#include <cuda_fp16.h>
#include <cstdint>

#define BATCH 8
#define DM 256
#define NH 4
#define HD 64
#define SEQ 2048
#define BH (BATCH*NH)

typedef unsigned short u16;

// Q: [bh][n][d] fp16 hi/lo (pre-scaled by 0.125*log2e) ; K: [bh][m][d] fp16 ; V: [bh][d][m] fp16
__device__ u16  g_qh[(size_t)BH*SEQ*HD];
__device__ u16  g_ql[(size_t)BH*SEQ*HD];
__device__ u16  g_kh[(size_t)BH*SEQ*HD];
__device__ u16  g_vh[(size_t)BH*HD*SEQ];
__device__ float g_x [(size_t)BATCH*DM*SEQ];
// pre-split weights: [mat][o][i] bf16 hi/lo
__device__ u16  g_wh[4*DM*DM];
__device__ u16  g_wl[4*DM*DM];

#define QSCALE 0.18033688011112042f   // 0.125 * log2(e)

__device__ __forceinline__ float ex2f(float x) {
    float r; asm("ex2.approx.f32 %0, %1;" : "=f"(r) : "f"(x)); return r;
}
__device__ __forceinline__ uint32_t packh2(float lo, float hi) {
    uint32_t r; asm("cvt.rn.f16x2.f32 %0, %1, %2;" : "=r"(r) : "f"(hi), "f"(lo)); return r;
}
__device__ __forceinline__ void split2(float v0, float v1, uint32_t& hp, uint32_t& lp) {
    asm("cvt.rn.bf16x2.f32 %0, %1, %2;" : "=r"(hp) : "f"(v1), "f"(v0));
    float f0 = __uint_as_float(hp << 16);
    float f1 = __uint_as_float(hp & 0xffff0000u);
    asm("cvt.rn.bf16x2.f32 %0, %1, %2;" : "=r"(lp) : "f"(v1 - f1), "f"(v0 - f0));
}
__device__ __forceinline__ void splithalf(float v, u16& h, u16& l) {
    __half hb = __float2half_rn(v);
    __half lb = __float2half_rn(v - __half2float(hb));
    h = __half_as_ushort(hb); l = __half_as_ushort(lb);
}
__device__ __forceinline__ void mma16816(float* d, const uint32_t* a, uint32_t b0, uint32_t b1) {
    asm volatile("mma.sync.aligned.m16n8k16.row.col.f32.bf16.bf16.f32 "
                 "{%0,%1,%2,%3}, {%4,%5,%6,%7}, {%8,%9}, {%0,%1,%2,%3};\n"
                 : "+f"(d[0]), "+f"(d[1]), "+f"(d[2]), "+f"(d[3])
                 : "r"(a[0]), "r"(a[1]), "r"(a[2]), "r"(a[3]), "r"(b0), "r"(b1));
}
__device__ __forceinline__ void mma16816h(float* d, const uint32_t* a, uint32_t b0, uint32_t b1) {
    asm volatile("mma.sync.aligned.m16n8k16.row.col.f32.f16.f16.f32 "
                 "{%0,%1,%2,%3}, {%4,%5,%6,%7}, {%8,%9}, {%0,%1,%2,%3};\n"
                 : "+f"(d[0]), "+f"(d[1]), "+f"(d[2]), "+f"(d[3])
                 : "r"(a[0]), "r"(a[1]), "r"(a[2]), "r"(a[3]), "r"(b0), "r"(b1));
}
__device__ __forceinline__ void ldsm4(uint32_t a, uint32_t& r0, uint32_t& r1,
                                      uint32_t& r2, uint32_t& r3) {
    asm volatile("ldmatrix.sync.aligned.m8n8.x4.shared.b16 {%0,%1,%2,%3}, [%4];"
                 : "=r"(r0), "=r"(r1), "=r"(r2), "=r"(r3) : "r"(a));
}
__device__ __forceinline__ void ldsm4t(uint32_t a, uint32_t& r0, uint32_t& r1,
                                       uint32_t& r2, uint32_t& r3) {
    asm volatile("ldmatrix.sync.aligned.m8n8.x4.trans.shared.b16 {%0,%1,%2,%3}, [%4];"
                 : "=r"(r0), "=r"(r1), "=r"(r2), "=r"(r3) : "r"(a));
}
__device__ __forceinline__ void cp16(uint32_t saddr, const void* g) {
    asm volatile("cp.async.ca.shared.global [%0], [%1], 16;" :: "r"(saddr), "l"(g));
}
#define CP_COMMIT() asm volatile("cp.async.commit_group;" ::: "memory")
#define CP_WAIT(n)  asm volatile("cp.async.wait_group %0;" :: "n"(n) : "memory")

// ---------------------------------------------------------------------------
// One-shot weight splitter: 4 x [256][256] fp32 -> bf16 hi/lo. Grid (32, 4).
// ---------------------------------------------------------------------------
__global__ __launch_bounds__(256)
void wsplit_kernel(const float* __restrict__ W0, const float* __restrict__ W1,
                   const float* __restrict__ W2, const float* __restrict__ W3,
                   u16* __restrict__ Wh, u16* __restrict__ Wl) {
    const int mat = blockIdx.y;
    const float* src = (mat == 0) ? W0 : (mat == 1) ? W1 : (mat == 2) ? W2 : W3;
    const size_t base = (size_t)mat * DM * DM;
    const int i0 = (blockIdx.x * 256 + threadIdx.x) * 8;
    #pragma unroll
    for (int p = 0; p < 2; p++) {
        float4 v = *(const float4*)&src[i0 + 4*p];
        uint32_t h01, l01, h23, l23;
        split2(v.x, v.y, h01, l01);
        split2(v.z, v.w, h23, l23);
        *(uint2*)&Wh[base + i0 + 4*p] = make_uint2(h01, h23);
        *(uint2*)&Wl[base + i0 + 4*p] = make_uint2(l01, l23);
    }
}

// ---------------------------------------------------------------------------
// Tensor-core projection (bf16 3-term), W pre-split in gmem, staged by cp.async.
// W smem pitch 80B (16B-aligned rows, conflict-free frag reads).
// MODE 0: fp32 [b][o][n]; MODE 1: fp16 hi/lo [bh][n][d], pre-scaled (Q);
// MODE 3: fp16 hi [bh][n][d] (K); MODE 2: fp16 hi [bh][d][m] (V).
// Grid (SEQ/64, DM/128, BATCH). 256 threads, 2 CTAs/SM.
// ---------------------------------------------------------------------------
#define PWH 0
#define PWL 10240
#define PXH 20480
#define PXL 25088
#define PSM_BYTES 34816   // epilogue Osm (128 x 68 f32) overlaps staging area

template<int MODE>
__global__ __launch_bounds__(256, 2)
void proj_tc(const u16* __restrict__ Wh, const u16* __restrict__ Wl,
             const float* __restrict__ bias,
             const float* __restrict__ X, float* __restrict__ C0,
             u16* __restrict__ Ch, u16* __restrict__ Cl) {
    __shared__ __align__(16) char psm[PSM_BYTES];
    __shared__ float biasSm[128];
    const uint32_t sbase = (uint32_t)__cvta_generic_to_shared(psm);
    const int n0 = blockIdx.x * 64, o0 = blockIdx.y * 128, b = blockIdx.z;
    const int tid = threadIdx.x;
    const int w = tid >> 5, l = tid & 31;
    const int g = l >> 2, tt = l & 3;
    if (tid < 128) biasSm[tid] = bias[o0 + tid];

    float O[8][4];
    #pragma unroll
    for (int i = 0; i < 8; i++) { O[i][0]=0.f; O[i][1]=0.f; O[i][2]=0.f; O[i][3]=0.f; }

    const uint32_t xoff = (uint32_t)((8*((l >> 3) & 1) + (l & 7)) * 144 + 16 * (l >> 4));
    const int wrow = tid >> 1, wpc = tid & 1;     // W cp.async map: 2 thr/row
    const int xn4 = (tid & 15) * 4;               // X stage map

    for (int c = 0; c < 8; c++) {
        const int k0 = c * 32;
        __syncthreads();
        // ---- stage W chunk [128 o][32 i] hi/lo via cp.async (pre-split)
        {
            const u16* sh = Wh + (size_t)(o0 + wrow) * DM + k0 + wpc * 16;
            const u16* sl = Wl + (size_t)(o0 + wrow) * DM + k0 + wpc * 16;
            const uint32_t dh = sbase + PWH + wrow * 80 + wpc * 32;
            const uint32_t dl = sbase + PWL + wrow * 80 + wpc * 32;
            cp16(dh,      sh);
            cp16(dh + 16, sh + 8);
            cp16(dl,      sl);
            cp16(dl + 16, sl + 8);
        }
        // ---- stage X chunk [32 i][64 n] split hi/lo (scalar; unique per CTA)
        #pragma unroll
        for (int p = 0; p < 2; p++) {
            const int i = p * 16 + (tid >> 4);
            float4 v = *(const float4*)&X[((size_t)b * DM + k0 + i) * SEQ + n0 + xn4];
            uint32_t h01, l01, h23, l23;
            split2(v.x, v.y, h01, l01);
            split2(v.z, v.w, h23, l23);
            *(uint2*)(psm + PXH + i*144 + xn4*2) = make_uint2(h01, h23);
            *(uint2*)(psm + PXL + i*144 + xn4*2) = make_uint2(l01, l23);
        }
        CP_COMMIT(); CP_WAIT(0);
        __syncthreads();
        // ---- compute: 2 k16 slabs
        #pragma unroll
        for (int s = 0; s < 2; s++) {
            uint32_t ah[4], al[4];
            const char* wp = psm + PWH + (w*16 + g)*80 + s*32 + tt*4;
            ah[0] = *(const uint32_t*)wp;
            ah[1] = *(const uint32_t*)(wp + 8*80);
            ah[2] = *(const uint32_t*)(wp + 16);
            ah[3] = *(const uint32_t*)(wp + 8*80 + 16);
            const char* wq = wp + (PWL - PWH);
            al[0] = *(const uint32_t*)wq;
            al[1] = *(const uint32_t*)(wq + 8*80);
            al[2] = *(const uint32_t*)(wq + 16);
            al[3] = *(const uint32_t*)(wq + 8*80 + 16);
            const uint32_t xb = sbase + PXH + s*2304 + xoff;
            #pragma unroll
            for (int nbp = 0; nbp < 4; nbp++) {
                uint32_t h0,h1,h2,h3, q0,q1,q2,q3;
                ldsm4t(xb + 32*nbp,               h0, h1, h2, h3);
                ldsm4t(xb + 32*nbp + (PXL - PXH), q0, q1, q2, q3);
                mma16816(O[2*nbp],   ah, h0, h1);
                mma16816(O[2*nbp],   ah, q0, q1);
                mma16816(O[2*nbp],   al, h0, h1);
                mma16816(O[2*nbp+1], ah, h2, h3);
                mma16816(O[2*nbp+1], ah, q2, q3);
                mma16816(O[2*nbp+1], al, h2, h3);
            }
        }
    }
    __syncthreads();
    float* Osm = (float*)psm;
    {
        const int r = w*16 + g;
        #pragma unroll
        for (int nb = 0; nb < 8; nb++) {
            const int cc = nb*8 + 2*tt;
            Osm[r*68 + cc]         = O[nb][0];
            Osm[r*68 + cc + 1]     = O[nb][1];
            Osm[(r+8)*68 + cc]     = O[nb][2];
            Osm[(r+8)*68 + cc + 1] = O[nb][3];
        }
    }
    __syncthreads();

    if (MODE == 0) {
        const int o = tid >> 1, half = (tid & 1) * 32;
        const float bi = biasSm[o];
        const float* src = Osm + o*68 + half;
        float* dst = C0 + ((size_t)b * DM + o0 + o) * SEQ + n0 + half;
        #pragma unroll
        for (int j = 0; j < 8; j++) {
            float4 v = *(const float4*)(src + 4*j);
            v.x += bi; v.y += bi; v.z += bi; v.w += bi;
            *(float4*)(dst + 4*j) = v;
        }
    } else if (MODE == 1) {
        const int n = tid >> 2, hh = tid & 3;
        u16 oh[32], ol[32];
        #pragma unroll
        for (int d = 0; d < 32; d++)
            splithalf((Osm[(4*d + hh)*68 + n] + biasSm[4*d + hh]) * QSCALE, oh[d], ol[d]);
        size_t dst = ((size_t)(b*NH + hh) * SEQ + n0 + n) * HD + (o0 >> 2);
        #pragma unroll
        for (int j = 0; j < 4; j++) {
            *(uint4*)(Ch + dst + 8*j) = *(uint4*)(oh + 8*j);
            *(uint4*)(Cl + dst + 8*j) = *(uint4*)(ol + 8*j);
        }
    } else if (MODE == 3) {
        const int n = tid >> 2, hh = tid & 3;
        u16 oh[32];
        #pragma unroll
        for (int d = 0; d < 32; d++)
            oh[d] = __half_as_ushort(__float2half_rn(Osm[(4*d + hh)*68 + n] + biasSm[4*d + hh]));
        size_t dst = ((size_t)(b*NH + hh) * SEQ + n0 + n) * HD + (o0 >> 2);
        #pragma unroll
        for (int j = 0; j < 4; j++)
            *(uint4*)(Ch + dst + 8*j) = *(uint4*)(oh + 8*j);
    } else {
        const int ol_ = tid >> 1, mh = (tid & 1) * 32;
        const int chn = o0 + ol_;
        const int d = chn >> 2, hh = chn & 3;
        const float bi = biasSm[ol_];
        const float* src = Osm + ol_*68 + mh;
        u16 xh[32];
        #pragma unroll
        for (int j = 0; j < 32; j++)
            xh[j] = __half_as_ushort(__float2half_rn(src[j] + bi));
        size_t dst = ((size_t)(b*NH + hh) * HD + d) * SEQ + n0 + mh;
        #pragma unroll
        for (int j = 0; j < 4; j++)
            *(uint4*)(Ch + dst + 8*j) = *(uint4*)(xh + 8*j);
    }
}

// ---------------------------------------------------------------------------
// Fused flash attention (reverted to R9's best): fp16, Q 2-term (pre-scaled),
// K/V/P single-term, ls via all-ones MMA. Double-buffered cp.async. 2 CTAs/SM.
// 256 threads = 8 warps x 16 q-rows. Grid (SEQ/128, BH). smem 106KB.
// ---------------------------------------------------------------------------
#define KPITCH 144
#define VPITCH 272
#define STG 35840            // K (18432) + V (17408) per stage
#define QOFF 71680           // Q hi at QOFF, Q lo at QOFF+18432
#define FLASH_SMEM 108544

__global__ __launch_bounds__(256, 2)
void flash_kernel(const u16* __restrict__ qh, const u16* __restrict__ ql,
                  const u16* __restrict__ kh, const u16* __restrict__ vh,
                  float* __restrict__ X) {
    extern __shared__ __align__(16) char sm[];
    const uint32_t sbase = (uint32_t)__cvta_generic_to_shared(sm);
    const int n0 = blockIdx.x * 128;
    const int bh = blockIdx.y;
    const int b = bh >> 2, h = bh & 3;
    const int t = threadIdx.x;
    const int w = t >> 5, l = t & 31;
    const int g = l >> 2, tt = l & 3;
    const uint32_t ONES = 0x3C003C00u;

    // copy maps
    const int km = t >> 1, khalf = (t & 1) * 32;
    const int vd = t >> 2, vm0 = (t & 3) * 32;
    const uint32_t kso = (uint32_t)(km * KPITCH + khalf * 2);
    const uint32_t vso = (uint32_t)(vd * VPITCH + vm0 * 2);
    const u16* kg = kh + ((size_t)bh*SEQ + km) * HD + khalf;
    const u16* vg = vh + ((size_t)bh*HD + vd) * SEQ + vm0;

    // ldmatrix lane-constant bases
    const uint32_t kfb = (uint32_t)((l & 7) * KPITCH + 16 * (l >> 3));
    const uint32_t vfb = (uint32_t)(((l & 7) + 8*(l >> 4)) * VPITCH + 16 * ((l >> 3) & 1));

    // ---- prologue: Q (hi+lo), then K0/V0, K1/V1
    {
        const u16* qgh = qh + ((size_t)bh*SEQ + n0 + km) * HD + khalf;
        const u16* qgl = ql + ((size_t)bh*SEQ + n0 + km) * HD + khalf;
        #pragma unroll
        for (int u = 0; u < 4; u++) {
            cp16(sbase + QOFF + kso + 16*u,         qgh + 8*u);
            cp16(sbase + QOFF + 18432 + kso + 16*u, qgl + 8*u);
        }
        CP_COMMIT();
        #pragma unroll
        for (int u = 0; u < 4; u++) {
            cp16(sbase + kso + 16*u,         kg + 8*u);
            cp16(sbase + 18432 + vso + 16*u, vg + 8*u);
        }
        CP_COMMIT();
        #pragma unroll
        for (int u = 0; u < 4; u++) {
            cp16(sbase + STG + kso + 16*u,         kg + (size_t)128*HD + 8*u);
            cp16(sbase + STG + 18432 + vso + 16*u, vg + 128 + 8*u);
        }
        CP_COMMIT();
    }
    CP_WAIT(2);
    __syncthreads();
    uint32_t qa_h[4][4], qa_l[4][4];
    {
        const char* QH = sm + QOFF;
        const char* QL = sm + QOFF + 18432;
        const int r0 = (16*w + g) * KPITCH;
        #pragma unroll
        for (int j = 0; j < 4; j++) {
            const int c = (16*j + 2*tt) * 2;
            qa_h[j][0] = *(const uint32_t*)(QH + r0 + c);
            qa_h[j][1] = *(const uint32_t*)(QH + r0 + 8*KPITCH + c);
            qa_h[j][2] = *(const uint32_t*)(QH + r0 + c + 16);
            qa_h[j][3] = *(const uint32_t*)(QH + r0 + 8*KPITCH + c + 16);
            qa_l[j][0] = *(const uint32_t*)(QL + r0 + c);
            qa_l[j][1] = *(const uint32_t*)(QL + r0 + 8*KPITCH + c);
            qa_l[j][2] = *(const uint32_t*)(QL + r0 + c + 16);
            qa_l[j][3] = *(const uint32_t*)(QL + r0 + 8*KPITCH + c + 16);
        }
    }

    float O[8][4];
    #pragma unroll
    for (int i = 0; i < 8; i++) { O[i][0]=0.f; O[i][1]=0.f; O[i][2]=0.f; O[i][3]=0.f; }
    float lsacc[4] = {0.f, 0.f, 0.f, 0.f};
    uint32_t phi[8][2];

    for (int it = 0; it < 16; it++) {
        if (it < 15) { CP_WAIT(1); } else { CP_WAIT(0); }
        __syncthreads();
        const uint32_t kb = sbase + (it & 1) * STG + kfb;
        const uint32_t vb = sbase + (it & 1) * STG + 18432 + vfb;

        #pragma unroll
        for (int half = 0; half < 2; half++) {
            // ---- S = (q_hi + q_lo) * k -> P
            #pragma unroll
            for (int mc = 0; mc < 8; mc++) {
                float sa[4] = {0.f,0.f,0.f,0.f};
                float sb[4] = {0.f,0.f,0.f,0.f};
                const uint32_t rbase = (uint32_t)((64*half + 8*mc) * KPITCH);
                uint32_t bh_[8];
                ldsm4(kb + rbase,      bh_[0], bh_[1], bh_[2], bh_[3]);
                ldsm4(kb + rbase + 64, bh_[4], bh_[5], bh_[6], bh_[7]);
                #pragma unroll
                for (int j = 0; j < 4; j++) {
                    mma16816h(sa, qa_h[j], bh_[2*j], bh_[2*j+1]);
                    mma16816h(sb, qa_l[j], bh_[2*j], bh_[2*j+1]);
                }
                float p0 = ex2f(sa[0] + sb[0]);
                float p1 = ex2f(sa[1] + sb[1]);
                float p2 = ex2f(sa[2] + sb[2]);
                float p3 = ex2f(sa[3] + sb[3]);
                phi[mc][0] = packh2(p0, p1);
                phi[mc][1] = packh2(p2, p3);
            }
            // ---- O += P * v ; ls += P * 1
            #pragma unroll
            for (int jj = 0; jj < 4; jj++) {
                uint32_t ah[4] = { phi[2*jj][0], phi[2*jj][1], phi[2*jj+1][0], phi[2*jj+1][1] };
                mma16816h(lsacc, ah, ONES, ONES);
                const uint32_t vcol = (uint32_t)(128*half + 32*jj);
                #pragma unroll
                for (int dcp = 0; dcp < 4; dcp++) {
                    uint32_t h0,h1,h2,h3;
                    ldsm4(vb + dcp*(16*VPITCH) + vcol, h0, h1, h2, h3);
                    mma16816h(O[2*dcp],   ah, h0, h1);
                    mma16816h(O[2*dcp+1], ah, h2, h3);
                }
            }
        }
        __syncthreads();   // all reads of buf[it&1] done
        if (it < 14) {     // stage (it+2) into buf[it&1]
            const u16* pk = kg + (size_t)(it + 2) * 128 * HD;
            const u16* pv = vg + (size_t)(it + 2) * 128;
            const uint32_t dk = sbase + (it & 1) * STG + kso;
            const uint32_t dv = sbase + (it & 1) * STG + 18432 + vso;
            #pragma unroll
            for (int u = 0; u < 4; u++) {
                cp16(dk + 16*u, pk + 8*u);
                cp16(dv + 16*u, pv + 8*u);
            }
            CP_COMMIT();
        }
    }

    const float i0 = 1.f / lsacc[0], i1 = 1.f / lsacc[2];
    #pragma unroll
    for (int dc = 0; dc < 8; dc++) {
        const int d0 = 8*dc + 2*tt;
        float* xp = X + ((size_t)b*DM + 4*d0 + h) * SEQ + n0 + 16*w;
        xp[g]             = O[dc][0] * i0;
        xp[4*SEQ + g]     = O[dc][1] * i0;
        xp[g + 8]         = O[dc][2] * i1;
        xp[4*SEQ + g + 8] = O[dc][3] * i1;
    }
}

// ---------------------------------------------------------------------------
extern "C" void kernel_launch(void* const* d_in, const int* in_sizes, int n_in,
                              void* d_out, int out_size) {
    const float* query = (const float*)d_in[0];
    const float* key   = (const float*)d_in[1];
    const float* value = (const float*)d_in[2];
    const float* Wq = (const float*)d_in[3];
    const float* bq = (const float*)d_in[4];
    const float* Wk = (const float*)d_in[5];
    const float* bk = (const float*)d_in[6];
    const float* Wv = (const float*)d_in[7];
    const float* bv = (const float*)d_in[8];
    const float* Wm = (const float*)d_in[9];
    const float* bm = (const float*)d_in[10];

    u16 *qh, *ql, *kh, *vh, *wh, *wl;
    float *x;
    cudaGetSymbolAddress((void**)&qh, g_qh);
    cudaGetSymbolAddress((void**)&ql, g_ql);
    cudaGetSymbolAddress((void**)&kh, g_kh);
    cudaGetSymbolAddress((void**)&vh, g_vh);
    cudaGetSymbolAddress((void**)&wh, g_wh);
    cudaGetSymbolAddress((void**)&wl, g_wl);
    cudaGetSymbolAddress((void**)&x,  g_x);

    cudaFuncSetAttribute(flash_kernel, cudaFuncAttributeMaxDynamicSharedMemorySize, FLASH_SMEM);

    wsplit_kernel<<<dim3(32, 4), 256>>>(Wq, Wk, Wv, Wm, wh, wl);

    dim3 pjGrid(SEQ/64, DM/128, BATCH);
    proj_tc<1><<<pjGrid, 256>>>(wh,            wl,            bq, query, nullptr, qh, ql);
    proj_tc<3><<<pjGrid, 256>>>(wh + DM*DM,    wl + DM*DM,    bk, key,   nullptr, kh, nullptr);
    proj_tc<2><<<pjGrid, 256>>>(wh + 2*DM*DM,  wl + 2*DM*DM,  bv, value, nullptr, vh, nullptr);

    flash_kernel<<<dim3(SEQ/128, BH), 256, FLASH_SMEM>>>(qh, ql, kh, vh, x);

    proj_tc<0><<<pjGrid, 256>>>(wh + 3*DM*DM,  wl + 3*DM*DM,  bm, x, (float*)d_out, nullptr, nullptr);
}

// round 12
// speedup vs baseline: 1.1499x; 1.0195x over previous
#include <cuda_runtime.h>
#include <cuda_bf16.h>
#include <cuda_fp16.h>
#include <cstdint>

#define BATCH 8
#define DM 256
#define NH 4
#define HD 64
#define SEQ 2048
#define BH (BATCH*NH)

typedef unsigned short u16;

// Q: [bh][n][d] fp16 hi/lo (pre-scaled by 0.125*log2e) ; K: [bh][m][d] fp16 ; V: [bh][d][m] fp16
__device__ u16  g_qh[(size_t)BH*SEQ*HD];
__device__ u16  g_ql[(size_t)BH*SEQ*HD];
__device__ u16  g_kh[(size_t)BH*SEQ*HD];
__device__ u16  g_vh[(size_t)BH*HD*SEQ];
__device__ float g_x [(size_t)BATCH*DM*SEQ];
// pre-split weights: [mat][o][i] bf16 hi/lo
__device__ u16  g_wh[4*DM*DM];
__device__ u16  g_wl[4*DM*DM];

#define QSCALE 0.18033688011112042f   // 0.125 * log2(e)

__device__ __forceinline__ float ex2f(float x) {
    float r; asm("ex2.approx.f32 %0, %1;" : "=f"(r) : "f"(x)); return r;
}
__device__ __forceinline__ uint32_t packh2(float lo, float hi) {
    uint32_t r; asm("cvt.rn.f16x2.f32 %0, %1, %2;" : "=r"(r) : "f"(hi), "f"(lo)); return r;
}
__device__ __forceinline__ void split2(float v0, float v1, uint32_t& hp, uint32_t& lp) {
    asm("cvt.rn.bf16x2.f32 %0, %1, %2;" : "=r"(hp) : "f"(v1), "f"(v0));
    float f0 = __uint_as_float(hp << 16);
    float f1 = __uint_as_float(hp & 0xffff0000u);
    asm("cvt.rn.bf16x2.f32 %0, %1, %2;" : "=r"(lp) : "f"(v1 - f1), "f"(v0 - f0));
}
__device__ __forceinline__ void splithalf(float v, u16& h, u16& l) {
    __half hb = __float2half_rn(v);
    __half lb = __float2half_rn(v - __half2float(hb));
    h = __half_as_ushort(hb); l = __half_as_ushort(lb);
}
__device__ __forceinline__ void mma16816(float* d, const uint32_t* a, uint32_t b0, uint32_t b1) {
    asm volatile("mma.sync.aligned.m16n8k16.row.col.f32.bf16.bf16.f32 "
                 "{%0,%1,%2,%3}, {%4,%5,%6,%7}, {%8,%9}, {%0,%1,%2,%3};\n"
                 : "+f"(d[0]), "+f"(d[1]), "+f"(d[2]), "+f"(d[3])
                 : "r"(a[0]), "r"(a[1]), "r"(a[2]), "r"(a[3]), "r"(b0), "r"(b1));
}
__device__ __forceinline__ void mma16816h(float* d, const uint32_t* a, uint32_t b0, uint32_t b1) {
    asm volatile("mma.sync.aligned.m16n8k16.row.col.f32.f16.f16.f32 "
                 "{%0,%1,%2,%3}, {%4,%5,%6,%7}, {%8,%9}, {%0,%1,%2,%3};\n"
                 : "+f"(d[0]), "+f"(d[1]), "+f"(d[2]), "+f"(d[3])
                 : "r"(a[0]), "r"(a[1]), "r"(a[2]), "r"(a[3]), "r"(b0), "r"(b1));
}
__device__ __forceinline__ void ldsm4(uint32_t a, uint32_t& r0, uint32_t& r1,
                                      uint32_t& r2, uint32_t& r3) {
    asm volatile("ldmatrix.sync.aligned.m8n8.x4.shared.b16 {%0,%1,%2,%3}, [%4];"
                 : "=r"(r0), "=r"(r1), "=r"(r2), "=r"(r3) : "r"(a));
}
__device__ __forceinline__ void ldsm4t(uint32_t a, uint32_t& r0, uint32_t& r1,
                                       uint32_t& r2, uint32_t& r3) {
    asm volatile("ldmatrix.sync.aligned.m8n8.x4.trans.shared.b16 {%0,%1,%2,%3}, [%4];"
                 : "=r"(r0), "=r"(r1), "=r"(r2), "=r"(r3) : "r"(a));
}
__device__ __forceinline__ void cp16(uint32_t saddr, const void* g) {
    asm volatile("cp.async.ca.shared.global [%0], [%1], 16;" :: "r"(saddr), "l"(g));
}
#define CP_COMMIT() asm volatile("cp.async.commit_group;" ::: "memory")
#define CP_WAIT(n)  asm volatile("cp.async.wait_group %0;" :: "n"(n) : "memory")

// ---------------------------------------------------------------------------
// One-shot weight splitter: 4 x [256][256] fp32 -> bf16 hi/lo. Grid (32, 4).
// ---------------------------------------------------------------------------
__global__ __launch_bounds__(256)
void wsplit_kernel(const float* __restrict__ W0, const float* __restrict__ W1,
                   const float* __restrict__ W2, const float* __restrict__ W3,
                   u16* __restrict__ Wh, u16* __restrict__ Wl) {
    const int mat = blockIdx.y;
    const float* src = (mat == 0) ? W0 : (mat == 1) ? W1 : (mat == 2) ? W2 : W3;
    const size_t base = (size_t)mat * DM * DM;
    const int i0 = (blockIdx.x * 256 + threadIdx.x) * 8;
    #pragma unroll
    for (int p = 0; p < 2; p++) {
        float4 v = *(const float4*)&src[i0 + 4*p];
        uint32_t h01, l01, h23, l23;
        split2(v.x, v.y, h01, l01);
        split2(v.z, v.w, h23, l23);
        *(uint2*)&Wh[base + i0 + 4*p] = make_uint2(h01, h23);
        *(uint2*)&Wl[base + i0 + 4*p] = make_uint2(l01, l23);
    }
}

// ---------------------------------------------------------------------------
// Tensor-core projection v4: bf16 3-term, pre-split W, double-buffered chunks.
// Per chunk (k=32): LDG(c+1) -> compute(c) -> STS(c+1), one sync per chunk.
// Dynamic smem 58KB (2 stages), 2 CTAs/SM. Grid (SEQ/64, DM/128, BATCH).
// MODE 0: fp32 [b][o][n]; MODE 1: fp16 hi/lo [bh][n][d], pre-scaled (Q);
// MODE 3: fp16 hi [bh][n][d] (K); MODE 2: fp16 hi [bh][d][m] (V).
// ---------------------------------------------------------------------------
#define PJ_W 10240                 // 128 rows x 80B (one of hi/lo)
#define PJ_X 4608                  // 32 rows x 144B (one of hi/lo)
#define PJSTG (2*PJ_W + 2*PJ_X)    // 29696 per stage
#define PJ_WH(s) ((s)*PJSTG)
#define PJ_WL(s) ((s)*PJSTG + PJ_W)
#define PJ_XH(s) ((s)*PJSTG + 2*PJ_W)
#define PJ_XL(s) ((s)*PJSTG + 2*PJ_W + PJ_X)
#define PSM_BYTES (2*PJSTG)        // 59392

template<int MODE>
__global__ __launch_bounds__(256, 2)
void proj_tc(const u16* __restrict__ Wh, const u16* __restrict__ Wl,
             const float* __restrict__ bias,
             const float* __restrict__ X, float* __restrict__ C0,
             u16* __restrict__ Ch, u16* __restrict__ Cl) {
    extern __shared__ __align__(16) char psm[];
    __shared__ float biasSm[128];
    const uint32_t sbase = (uint32_t)__cvta_generic_to_shared(psm);
    const int n0 = blockIdx.x * 64, o0 = blockIdx.y * 128, b = blockIdx.z;
    const int tid = threadIdx.x;
    const int w = tid >> 5, l = tid & 31;
    const int g = l >> 2, tt = l & 3;
    if (tid < 128) biasSm[tid] = bias[o0 + tid];

    float O[8][4];
    #pragma unroll
    for (int i = 0; i < 8; i++) { O[i][0]=0.f; O[i][1]=0.f; O[i][2]=0.f; O[i][3]=0.f; }

    const uint32_t xoff = (uint32_t)((8*((l >> 3) & 1) + (l & 7)) * 144 + 16 * (l >> 4));
    const int wrow = tid >> 1, wpc = tid & 1;     // W: 2 threads/row, 32B each
    const int xrow = tid >> 4, xn4 = (tid & 15) * 4;

    const u16* wsrcH = Wh + (size_t)(o0 + wrow) * DM + wpc * 16;
    const u16* wsrcL = Wl + (size_t)(o0 + wrow) * DM + wpc * 16;
    const float* xsrc = X + ((size_t)b * DM + xrow) * SEQ + n0 + xn4;

    uint4 rwh0, rwh1, rwl0, rwl1;
    float4 rx0, rx1;

    #define PJ_FETCH(c) do { \
        rwh0 = *(const uint4*)(wsrcH + (c)*32); \
        rwh1 = *(const uint4*)(wsrcH + (c)*32 + 8); \
        rwl0 = *(const uint4*)(wsrcL + (c)*32); \
        rwl1 = *(const uint4*)(wsrcL + (c)*32 + 8); \
        rx0 = *(const float4*)(xsrc + (size_t)((c)*32) * SEQ); \
        rx1 = *(const float4*)(xsrc + (size_t)((c)*32 + 16) * SEQ); \
    } while (0)

    #define PJ_STORE(s) do { \
        *(uint4*)(psm + PJ_WH(s) + wrow*80 + wpc*32)      = rwh0; \
        *(uint4*)(psm + PJ_WH(s) + wrow*80 + wpc*32 + 16) = rwh1; \
        *(uint4*)(psm + PJ_WL(s) + wrow*80 + wpc*32)      = rwl0; \
        *(uint4*)(psm + PJ_WL(s) + wrow*80 + wpc*32 + 16) = rwl1; \
        uint32_t h01, l01, h23, l23; \
        split2(rx0.x, rx0.y, h01, l01); split2(rx0.z, rx0.w, h23, l23); \
        *(uint2*)(psm + PJ_XH(s) + xrow*144 + xn4*2) = make_uint2(h01, h23); \
        *(uint2*)(psm + PJ_XL(s) + xrow*144 + xn4*2) = make_uint2(l01, l23); \
        split2(rx1.x, rx1.y, h01, l01); split2(rx1.z, rx1.w, h23, l23); \
        *(uint2*)(psm + PJ_XH(s) + (16 + xrow)*144 + xn4*2) = make_uint2(h01, h23); \
        *(uint2*)(psm + PJ_XL(s) + (16 + xrow)*144 + xn4*2) = make_uint2(l01, l23); \
    } while (0)

    // prologue: stage chunk 0 into stage 0
    PJ_FETCH(0);
    PJ_STORE(0);
    __syncthreads();

    for (int c = 0; c < 8; c++) {
        const int cur = c & 1;
        if (c < 7) PJ_FETCH(c + 1);          // LDGs in flight over compute
        // ---- compute chunk c: 2 k16 slabs
        #pragma unroll
        for (int s = 0; s < 2; s++) {
            uint32_t ah[4], al[4];
            const char* wp = psm + PJ_WH(cur) + (w*16 + g)*80 + s*32 + tt*4;
            ah[0] = *(const uint32_t*)wp;
            ah[1] = *(const uint32_t*)(wp + 8*80);
            ah[2] = *(const uint32_t*)(wp + 16);
            ah[3] = *(const uint32_t*)(wp + 8*80 + 16);
            const char* wq = wp + PJ_W;
            al[0] = *(const uint32_t*)wq;
            al[1] = *(const uint32_t*)(wq + 8*80);
            al[2] = *(const uint32_t*)(wq + 16);
            al[3] = *(const uint32_t*)(wq + 8*80 + 16);
            const uint32_t xb = sbase + PJ_XH(cur) + s*2304 + xoff;
            #pragma unroll
            for (int nbp = 0; nbp < 4; nbp++) {
                uint32_t h0,h1,h2,h3, q0,q1,q2,q3;
                ldsm4t(xb + 32*nbp,        h0, h1, h2, h3);
                ldsm4t(xb + 32*nbp + PJ_X, q0, q1, q2, q3);
                mma16816(O[2*nbp],   ah, h0, h1);
                mma16816(O[2*nbp],   ah, q0, q1);
                mma16816(O[2*nbp],   al, h0, h1);
                mma16816(O[2*nbp+1], ah, h2, h3);
                mma16816(O[2*nbp+1], ah, q2, q3);
                mma16816(O[2*nbp+1], al, h2, h3);
            }
        }
        if (c < 7) PJ_STORE(1 - cur);
        __syncthreads();
    }
    #undef PJ_FETCH
    #undef PJ_STORE

    // ---- epilogue: O -> smem [128 o][68 pitch] fp32 (reuses stage area)
    float* Osm = (float*)psm;
    {
        const int r = w*16 + g;
        #pragma unroll
        for (int nb = 0; nb < 8; nb++) {
            const int cc = nb*8 + 2*tt;
            Osm[r*68 + cc]         = O[nb][0];
            Osm[r*68 + cc + 1]     = O[nb][1];
            Osm[(r+8)*68 + cc]     = O[nb][2];
            Osm[(r+8)*68 + cc + 1] = O[nb][3];
        }
    }
    __syncthreads();

    if (MODE == 0) {
        const int o = tid >> 1, half = (tid & 1) * 32;
        const float bi = biasSm[o];
        const float* src = Osm + o*68 + half;
        float* dst = C0 + ((size_t)b * DM + o0 + o) * SEQ + n0 + half;
        #pragma unroll
        for (int j = 0; j < 8; j++) {
            float4 v = *(const float4*)(src + 4*j);
            v.x += bi; v.y += bi; v.z += bi; v.w += bi;
            *(float4*)(dst + 4*j) = v;
        }
    } else if (MODE == 1) {
        const int n = tid >> 2, hh = tid & 3;
        u16 oh[32], ol[32];
        #pragma unroll
        for (int d = 0; d < 32; d++)
            splithalf((Osm[(4*d + hh)*68 + n] + biasSm[4*d + hh]) * QSCALE, oh[d], ol[d]);
        size_t dst = ((size_t)(b*NH + hh) * SEQ + n0 + n) * HD + (o0 >> 2);
        #pragma unroll
        for (int j = 0; j < 4; j++) {
            *(uint4*)(Ch + dst + 8*j) = *(uint4*)(oh + 8*j);
            *(uint4*)(Cl + dst + 8*j) = *(uint4*)(ol + 8*j);
        }
    } else if (MODE == 3) {
        const int n = tid >> 2, hh = tid & 3;
        u16 oh[32];
        #pragma unroll
        for (int d = 0; d < 32; d++)
            oh[d] = __half_as_ushort(__float2half_rn(Osm[(4*d + hh)*68 + n] + biasSm[4*d + hh]));
        size_t dst = ((size_t)(b*NH + hh) * SEQ + n0 + n) * HD + (o0 >> 2);
        #pragma unroll
        for (int j = 0; j < 4; j++)
            *(uint4*)(Ch + dst + 8*j) = *(uint4*)(oh + 8*j);
    } else {
        const int ol_ = tid >> 1, mh = (tid & 1) * 32;
        const int chn = o0 + ol_;
        const int d = chn >> 2, hh = chn & 3;
        const float bi = biasSm[ol_];
        const float* src = Osm + ol_*68 + mh;
        u16 xh[32];
        #pragma unroll
        for (int j = 0; j < 32; j++)
            xh[j] = __half_as_ushort(__float2half_rn(src[j] + bi));
        size_t dst = ((size_t)(b*NH + hh) * HD + d) * SEQ + n0 + mh;
        #pragma unroll
        for (int j = 0; j < 4; j++)
            *(uint4*)(Ch + dst + 8*j) = *(uint4*)(xh + 8*j);
    }
}

// ---------------------------------------------------------------------------
// Fused flash attention (R9 best, unchanged): fp16, Q 2-term (pre-scaled),
// K/V/P single-term, ls via all-ones MMA. Double-buffered cp.async. 2 CTAs/SM.
// 256 threads = 8 warps x 16 q-rows. Grid (SEQ/128, BH). smem 106KB.
// ---------------------------------------------------------------------------
#define KPITCH 144
#define VPITCH 272
#define STG 35840            // K (18432) + V (17408) per stage
#define QOFF 71680           // Q hi at QOFF, Q lo at QOFF+18432
#define FLASH_SMEM 108544

__global__ __launch_bounds__(256, 2)
void flash_kernel(const u16* __restrict__ qh, const u16* __restrict__ ql,
                  const u16* __restrict__ kh, const u16* __restrict__ vh,
                  float* __restrict__ X) {
    extern __shared__ __align__(16) char sm[];
    const uint32_t sbase = (uint32_t)__cvta_generic_to_shared(sm);
    const int n0 = blockIdx.x * 128;
    const int bh = blockIdx.y;
    const int b = bh >> 2, h = bh & 3;
    const int t = threadIdx.x;
    const int w = t >> 5, l = t & 31;
    const int g = l >> 2, tt = l & 3;
    const uint32_t ONES = 0x3C003C00u;

    const int km = t >> 1, khalf = (t & 1) * 32;
    const int vd = t >> 2, vm0 = (t & 3) * 32;
    const uint32_t kso = (uint32_t)(km * KPITCH + khalf * 2);
    const uint32_t vso = (uint32_t)(vd * VPITCH + vm0 * 2);
    const u16* kg = kh + ((size_t)bh*SEQ + km) * HD + khalf;
    const u16* vg = vh + ((size_t)bh*HD + vd) * SEQ + vm0;

    const uint32_t kfb = (uint32_t)((l & 7) * KPITCH + 16 * (l >> 3));
    const uint32_t vfb = (uint32_t)(((l & 7) + 8*(l >> 4)) * VPITCH + 16 * ((l >> 3) & 1));

    {
        const u16* qgh = qh + ((size_t)bh*SEQ + n0 + km) * HD + khalf;
        const u16* qgl = ql + ((size_t)bh*SEQ + n0 + km) * HD + khalf;
        #pragma unroll
        for (int u = 0; u < 4; u++) {
            cp16(sbase + QOFF + kso + 16*u,         qgh + 8*u);
            cp16(sbase + QOFF + 18432 + kso + 16*u, qgl + 8*u);
        }
        CP_COMMIT();
        #pragma unroll
        for (int u = 0; u < 4; u++) {
            cp16(sbase + kso + 16*u,         kg + 8*u);
            cp16(sbase + 18432 + vso + 16*u, vg + 8*u);
        }
        CP_COMMIT();
        #pragma unroll
        for (int u = 0; u < 4; u++) {
            cp16(sbase + STG + kso + 16*u,         kg + (size_t)128*HD + 8*u);
            cp16(sbase + STG + 18432 + vso + 16*u, vg + 128 + 8*u);
        }
        CP_COMMIT();
    }
    CP_WAIT(2);
    __syncthreads();
    uint32_t qa_h[4][4], qa_l[4][4];
    {
        const char* QH = sm + QOFF;
        const char* QL = sm + QOFF + 18432;
        const int r0 = (16*w + g) * KPITCH;
        #pragma unroll
        for (int j = 0; j < 4; j++) {
            const int c = (16*j + 2*tt) * 2;
            qa_h[j][0] = *(const uint32_t*)(QH + r0 + c);
            qa_h[j][1] = *(const uint32_t*)(QH + r0 + 8*KPITCH + c);
            qa_h[j][2] = *(const uint32_t*)(QH + r0 + c + 16);
            qa_h[j][3] = *(const uint32_t*)(QH + r0 + 8*KPITCH + c + 16);
            qa_l[j][0] = *(const uint32_t*)(QL + r0 + c);
            qa_l[j][1] = *(const uint32_t*)(QL + r0 + 8*KPITCH + c);
            qa_l[j][2] = *(const uint32_t*)(QL + r0 + c + 16);
            qa_l[j][3] = *(const uint32_t*)(QL + r0 + 8*KPITCH + c + 16);
        }
    }

    float O[8][4];
    #pragma unroll
    for (int i = 0; i < 8; i++) { O[i][0]=0.f; O[i][1]=0.f; O[i][2]=0.f; O[i][3]=0.f; }
    float lsacc[4] = {0.f, 0.f, 0.f, 0.f};
    uint32_t phi[8][2];

    for (int it = 0; it < 16; it++) {
        if (it < 15) { CP_WAIT(1); } else { CP_WAIT(0); }
        __syncthreads();
        const uint32_t kb = sbase + (it & 1) * STG + kfb;
        const uint32_t vb = sbase + (it & 1) * STG + 18432 + vfb;

        #pragma unroll
        for (int half = 0; half < 2; half++) {
            #pragma unroll
            for (int mc = 0; mc < 8; mc++) {
                float sa[4] = {0.f,0.f,0.f,0.f};
                float sb[4] = {0.f,0.f,0.f,0.f};
                const uint32_t rbase = (uint32_t)((64*half + 8*mc) * KPITCH);
                uint32_t bh_[8];
                ldsm4(kb + rbase,      bh_[0], bh_[1], bh_[2], bh_[3]);
                ldsm4(kb + rbase + 64, bh_[4], bh_[5], bh_[6], bh_[7]);
                #pragma unroll
                for (int j = 0; j < 4; j++) {
                    mma16816h(sa, qa_h[j], bh_[2*j], bh_[2*j+1]);
                    mma16816h(sb, qa_l[j], bh_[2*j], bh_[2*j+1]);
                }
                float p0 = ex2f(sa[0] + sb[0]);
                float p1 = ex2f(sa[1] + sb[1]);
                float p2 = ex2f(sa[2] + sb[2]);
                float p3 = ex2f(sa[3] + sb[3]);
                phi[mc][0] = packh2(p0, p1);
                phi[mc][1] = packh2(p2, p3);
            }
            #pragma unroll
            for (int jj = 0; jj < 4; jj++) {
                uint32_t ah[4] = { phi[2*jj][0], phi[2*jj][1], phi[2*jj+1][0], phi[2*jj+1][1] };
                mma16816h(lsacc, ah, ONES, ONES);
                const uint32_t vcol = (uint32_t)(128*half + 32*jj);
                #pragma unroll
                for (int dcp = 0; dcp < 4; dcp++) {
                    uint32_t h0,h1,h2,h3;
                    ldsm4(vb + dcp*(16*VPITCH) + vcol, h0, h1, h2, h3);
                    mma16816h(O[2*dcp],   ah, h0, h1);
                    mma16816h(O[2*dcp+1], ah, h2, h3);
                }
            }
        }
        __syncthreads();
        if (it < 14) {
            const u16* pk = kg + (size_t)(it + 2) * 128 * HD;
            const u16* pv = vg + (size_t)(it + 2) * 128;
            const uint32_t dk = sbase + (it & 1) * STG + kso;
            const uint32_t dv = sbase + (it & 1) * STG + 18432 + vso;
            #pragma unroll
            for (int u = 0; u < 4; u++) {
                cp16(dk + 16*u, pk + 8*u);
                cp16(dv + 16*u, pv + 8*u);
            }
            CP_COMMIT();
        }
    }

    const float i0 = 1.f / lsacc[0], i1 = 1.f / lsacc[2];
    #pragma unroll
    for (int dc = 0; dc < 8; dc++) {
        const int d0 = 8*dc + 2*tt;
        float* xp = X + ((size_t)b*DM + 4*d0 + h) * SEQ + n0 + 16*w;
        xp[g]             = O[dc][0] * i0;
        xp[4*SEQ + g]     = O[dc][1] * i0;
        xp[g + 8]         = O[dc][2] * i1;
        xp[4*SEQ + g + 8] = O[dc][3] * i1;
    }
}

// ---------------------------------------------------------------------------
extern "C" void kernel_launch(void* const* d_in, const int* in_sizes, int n_in,
                              void* d_out, int out_size) {
    const float* query = (const float*)d_in[0];
    const float* key   = (const float*)d_in[1];
    const float* value = (const float*)d_in[2];
    const float* Wq = (const float*)d_in[3];
    const float* bq = (const float*)d_in[4];
    const float* Wk = (const float*)d_in[5];
    const float* bk = (const float*)d_in[6];
    const float* Wv = (const float*)d_in[7];
    const float* bv = (const float*)d_in[8];
    const float* Wm = (const float*)d_in[9];
    const float* bm = (const float*)d_in[10];

    u16 *qh, *ql, *kh, *vh, *wh, *wl;
    float *x;
    cudaGetSymbolAddress((void**)&qh, g_qh);
    cudaGetSymbolAddress((void**)&ql, g_ql);
    cudaGetSymbolAddress((void**)&kh, g_kh);
    cudaGetSymbolAddress((void**)&vh, g_vh);
    cudaGetSymbolAddress((void**)&wh, g_wh);
    cudaGetSymbolAddress((void**)&wl, g_wl);
    cudaGetSymbolAddress((void**)&x,  g_x);

    cudaFuncSetAttribute(flash_kernel, cudaFuncAttributeMaxDynamicSharedMemorySize, FLASH_SMEM);
    cudaFuncSetAttribute(proj_tc<0>, cudaFuncAttributeMaxDynamicSharedMemorySize, PSM_BYTES);
    cudaFuncSetAttribute(proj_tc<1>, cudaFuncAttributeMaxDynamicSharedMemorySize, PSM_BYTES);
    cudaFuncSetAttribute(proj_tc<2>, cudaFuncAttributeMaxDynamicSharedMemorySize, PSM_BYTES);
    cudaFuncSetAttribute(proj_tc<3>, cudaFuncAttributeMaxDynamicSharedMemorySize, PSM_BYTES);

    wsplit_kernel<<<dim3(32, 4), 256>>>(Wq, Wk, Wv, Wm, wh, wl);

    dim3 pjGrid(SEQ/64, DM/128, BATCH);
    proj_tc<1><<<pjGrid, 256, PSM_BYTES>>>(wh,           wl,           bq, query, nullptr, qh, ql);
    proj_tc<3><<<pjGrid, 256, PSM_BYTES>>>(wh + DM*DM,   wl + DM*DM,   bk, key,   nullptr, kh, nullptr);
    proj_tc<2><<<pjGrid, 256, PSM_BYTES>>>(wh + 2*DM*DM, wl + 2*DM*DM, bv, value, nullptr, vh, nullptr);

    flash_kernel<<<dim3(SEQ/128, BH), 256, FLASH_SMEM>>>(qh, ql, kh, vh, x);

    proj_tc<0><<<pjGrid, 256, PSM_BYTES>>>(wh + 3*DM*DM, wl + 3*DM*DM, bm, x, (float*)d_out, nullptr, nullptr);
}

// round 13
// speedup vs baseline: 1.3322x; 1.1585x over previous
#include <cuda_runtime.h>
#include <cuda_bf16.h>
#include <cuda_fp16.h>
#include <cstdint>

#define BATCH 8
#define DM 256
#define NH 4
#define HD 64
#define SEQ 2048
#define BH (BATCH*NH)

typedef unsigned short u16;

// Q: [bh][n][d] fp16 hi/lo (pre-scaled by 0.125*log2e) ; K: [bh][m][d] fp16 ; V: [bh][d][m] fp16
__device__ u16  g_qh[(size_t)BH*SEQ*HD];
__device__ u16  g_ql[(size_t)BH*SEQ*HD];
__device__ u16  g_kh[(size_t)BH*SEQ*HD];
__device__ u16  g_vh[(size_t)BH*HD*SEQ];
__device__ float g_x [(size_t)BATCH*DM*SEQ];
// pre-split weights: [mat][o][i] fp16 hi/lo
__device__ u16  g_wh[4*DM*DM];
__device__ u16  g_wl[4*DM*DM];

#define QSCALE 0.18033688011112042f   // 0.125 * log2(e)

__device__ __forceinline__ float ex2f(float x) {
    float r; asm("ex2.approx.f32 %0, %1;" : "=f"(r) : "f"(x)); return r;
}
__device__ __forceinline__ uint32_t packh2(float lo, float hi) {
    uint32_t r; asm("cvt.rn.f16x2.f32 %0, %1, %2;" : "=r"(r) : "f"(hi), "f"(lo)); return r;
}
__device__ __forceinline__ void splithalf(float v, u16& h, u16& l) {
    __half hb = __float2half_rn(v);
    __half lb = __float2half_rn(v - __half2float(hb));
    h = __half_as_ushort(hb); l = __half_as_ushort(lb);
}
__device__ __forceinline__ void mma16816h(float* d, const uint32_t* a, uint32_t b0, uint32_t b1) {
    asm volatile("mma.sync.aligned.m16n8k16.row.col.f32.f16.f16.f32 "
                 "{%0,%1,%2,%3}, {%4,%5,%6,%7}, {%8,%9}, {%0,%1,%2,%3};\n"
                 : "+f"(d[0]), "+f"(d[1]), "+f"(d[2]), "+f"(d[3])
                 : "r"(a[0]), "r"(a[1]), "r"(a[2]), "r"(a[3]), "r"(b0), "r"(b1));
}
__device__ __forceinline__ void ldsm4(uint32_t a, uint32_t& r0, uint32_t& r1,
                                      uint32_t& r2, uint32_t& r3) {
    asm volatile("ldmatrix.sync.aligned.m8n8.x4.shared.b16 {%0,%1,%2,%3}, [%4];"
                 : "=r"(r0), "=r"(r1), "=r"(r2), "=r"(r3) : "r"(a));
}
__device__ __forceinline__ void ldsm4t(uint32_t a, uint32_t& r0, uint32_t& r1,
                                       uint32_t& r2, uint32_t& r3) {
    asm volatile("ldmatrix.sync.aligned.m8n8.x4.trans.shared.b16 {%0,%1,%2,%3}, [%4];"
                 : "=r"(r0), "=r"(r1), "=r"(r2), "=r"(r3) : "r"(a));
}
__device__ __forceinline__ void cp16(uint32_t saddr, const void* g) {
    asm volatile("cp.async.ca.shared.global [%0], [%1], 16;" :: "r"(saddr), "l"(g));
}
#define CP_COMMIT() asm volatile("cp.async.commit_group;" ::: "memory")
#define CP_WAIT(n)  asm volatile("cp.async.wait_group %0;" :: "n"(n) : "memory")

// ---------------------------------------------------------------------------
// One-shot weight splitter: 4 x [256][256] fp32 -> fp16 hi/lo. Grid (32, 4).
// ---------------------------------------------------------------------------
__global__ __launch_bounds__(256)
void wsplit_kernel(const float* __restrict__ W0, const float* __restrict__ W1,
                   const float* __restrict__ W2, const float* __restrict__ W3,
                   u16* __restrict__ Wh, u16* __restrict__ Wl) {
    const int mat = blockIdx.y;
    const float* src = (mat == 0) ? W0 : (mat == 1) ? W1 : (mat == 2) ? W2 : W3;
    const size_t base = (size_t)mat * DM * DM;
    const int i0 = (blockIdx.x * 256 + threadIdx.x) * 8;
    u16 h8[8], l8[8];
    #pragma unroll
    for (int p = 0; p < 8; p++)
        splithalf(src[i0 + p], h8[p], l8[p]);
    *(uint4*)&Wh[base + i0] = *(uint4*)h8;
    *(uint4*)&Wl[base + i0] = *(uint4*)l8;
}

// ---------------------------------------------------------------------------
// Tensor-core projection v5: fp16 2-term (W = Wh + Wl pre-split; X fp16 hi).
// Tile 128o x 128n -> 256 CTAs = ONE wave at 2 CTAs/SM.
// Per chunk (k=32): cp.async W(c+1) + LDG X(c+1) -> compute(c) -> STS X(c+1).
// MODE 0: fp32 [b][o][n]; MODE 1: fp16 hi/lo [bh][n][d], pre-scaled (Q);
// MODE 3: fp16 hi [bh][n][d] (K); MODE 2: fp16 hi [bh][d][m] (V).
// Grid (SEQ/128, DM/128, BATCH). 256 threads.
// ---------------------------------------------------------------------------
#define PJ_W 10240                 // 128 rows x 80B (one of hi/lo)
#define PJ_X 8704                  // 32 rows x 272B (fp16 hi only)
#define PJSTG (2*PJ_W + PJ_X)      // 29184 per stage
#define PJ_WH(s) ((s)*PJSTG)
#define PJ_WL(s) ((s)*PJSTG + PJ_W)
#define PJ_XH(s) ((s)*PJSTG + 2*PJ_W)
#define PSM_BYTES 69632            // epilogue Osm 128 x 136 f32 dominates

template<int MODE>
__global__ __launch_bounds__(256, 2)
void proj_tc(const u16* __restrict__ Wh, const u16* __restrict__ Wl,
             const float* __restrict__ bias,
             const float* __restrict__ X, float* __restrict__ C0,
             u16* __restrict__ Ch, u16* __restrict__ Cl) {
    extern __shared__ __align__(16) char psm[];
    __shared__ float biasSm[128];
    const uint32_t sbase = (uint32_t)__cvta_generic_to_shared(psm);
    const int n0 = blockIdx.x * 128, o0 = blockIdx.y * 128, b = blockIdx.z;
    const int tid = threadIdx.x;
    const int w = tid >> 5, l = tid & 31;
    const int g = l >> 2, tt = l & 3;
    if (tid < 128) biasSm[tid] = bias[o0 + tid];

    float O[16][4];
    #pragma unroll
    for (int i = 0; i < 16; i++) { O[i][0]=0.f; O[i][1]=0.f; O[i][2]=0.f; O[i][3]=0.f; }

    const uint32_t xoff = (uint32_t)((8*((l >> 3) & 1) + (l & 7)) * 272 + 16 * (l >> 4));
    const int wrow = tid >> 1, wpc = tid & 1;        // W: 2 threads/row, 32B each
    const int xrow = tid >> 3, xn16 = (tid & 7) * 16;

    const u16* wsH = Wh + (size_t)(o0 + wrow) * DM + wpc * 16;
    const u16* wsL = Wl + (size_t)(o0 + wrow) * DM + wpc * 16;
    const float* xsrc = X + ((size_t)b * DM + xrow) * SEQ + n0 + xn16;
    const uint32_t wdh = sbase + wrow * 80 + wpc * 32;

    float4 rx0, rx1, rx2, rx3;

    #define PJ_WCP(c, s) do { \
        cp16(wdh + PJ_WH(s),          wsH + (c)*32); \
        cp16(wdh + PJ_WH(s) + 16,     wsH + (c)*32 + 8); \
        cp16(wdh + PJ_WL(s),          wsL + (c)*32); \
        cp16(wdh + PJ_WL(s) + 16,     wsL + (c)*32 + 8); \
        CP_COMMIT(); \
    } while (0)
    #define PJ_XFETCH(c) do { \
        const float* xp_ = xsrc + (size_t)((c)*32) * SEQ; \
        rx0 = *(const float4*)(xp_);      rx1 = *(const float4*)(xp_ + 4); \
        rx2 = *(const float4*)(xp_ + 8);  rx3 = *(const float4*)(xp_ + 12); \
    } while (0)
    #define PJ_XSTORE(s) do { \
        uint32_t a0 = packh2(rx0.x, rx0.y), a1 = packh2(rx0.z, rx0.w); \
        uint32_t a2 = packh2(rx1.x, rx1.y), a3 = packh2(rx1.z, rx1.w); \
        uint32_t a4 = packh2(rx2.x, rx2.y), a5 = packh2(rx2.z, rx2.w); \
        uint32_t a6 = packh2(rx3.x, rx3.y), a7 = packh2(rx3.z, rx3.w); \
        char* xd_ = psm + PJ_XH(s) + xrow*272 + xn16*2; \
        *(uint4*)(xd_)      = make_uint4(a0, a1, a2, a3); \
        *(uint4*)(xd_ + 16) = make_uint4(a4, a5, a6, a7); \
    } while (0)

    // prologue: chunk 0 into stage 0
    PJ_WCP(0, 0);
    PJ_XFETCH(0);
    PJ_XSTORE(0);
    CP_WAIT(0);
    __syncthreads();

    for (int c = 0; c < 8; c++) {
        const int cur = c & 1;
        if (c < 7) { PJ_WCP(c + 1, 1 - cur); PJ_XFETCH(c + 1); }
        // ---- compute chunk c: 2 k16 slabs
        #pragma unroll
        for (int s = 0; s < 2; s++) {
            uint32_t ah[4], al[4];
            const char* wp = psm + PJ_WH(cur) + (w*16 + g)*80 + s*32 + tt*4;
            ah[0] = *(const uint32_t*)wp;
            ah[1] = *(const uint32_t*)(wp + 8*80);
            ah[2] = *(const uint32_t*)(wp + 16);
            ah[3] = *(const uint32_t*)(wp + 8*80 + 16);
            const char* wq = wp + PJ_W;
            al[0] = *(const uint32_t*)wq;
            al[1] = *(const uint32_t*)(wq + 8*80);
            al[2] = *(const uint32_t*)(wq + 16);
            al[3] = *(const uint32_t*)(wq + 8*80 + 16);
            const uint32_t xb = sbase + PJ_XH(cur) + s*4352 + xoff;
            #pragma unroll
            for (int nbp = 0; nbp < 8; nbp++) {
                uint32_t h0, h1, h2, h3;
                ldsm4t(xb + 32*nbp, h0, h1, h2, h3);
                mma16816h(O[2*nbp],   ah, h0, h1);
                mma16816h(O[2*nbp+1], ah, h2, h3);
                mma16816h(O[2*nbp],   al, h0, h1);
                mma16816h(O[2*nbp+1], al, h2, h3);
            }
        }
        if (c < 7) { PJ_XSTORE(1 - cur); CP_WAIT(0); }
        __syncthreads();
    }
    #undef PJ_WCP
    #undef PJ_XFETCH
    #undef PJ_XSTORE

    // ---- epilogue: O -> smem [128 o][136 pitch] fp32 (reuses stage area)
    float* Osm = (float*)psm;
    {
        const int r = w*16 + g;
        #pragma unroll
        for (int nb = 0; nb < 16; nb++) {
            const int cc = nb*8 + 2*tt;
            Osm[r*136 + cc]         = O[nb][0];
            Osm[r*136 + cc + 1]     = O[nb][1];
            Osm[(r+8)*136 + cc]     = O[nb][2];
            Osm[(r+8)*136 + cc + 1] = O[nb][3];
        }
    }
    __syncthreads();

    if (MODE == 0) {
        const int o = tid >> 1, half = (tid & 1) * 64;
        const float bi = biasSm[o];
        const float* src = Osm + o*136 + half;
        float* dst = C0 + ((size_t)b * DM + o0 + o) * SEQ + n0 + half;
        #pragma unroll
        for (int j = 0; j < 16; j++) {
            float4 v = *(const float4*)(src + 4*j);
            v.x += bi; v.y += bi; v.z += bi; v.w += bi;
            *(float4*)(dst + 4*j) = v;
        }
    } else if (MODE == 1) {
        #pragma unroll
        for (int r = 0; r < 2; r++) {
            const int task = tid + 256*r;
            const int n = task >> 2, hh = task & 3;
            u16 oh[32], ol[32];
            #pragma unroll
            for (int d = 0; d < 32; d++)
                splithalf((Osm[(4*d + hh)*136 + n] + biasSm[4*d + hh]) * QSCALE, oh[d], ol[d]);
            size_t dst = ((size_t)(b*NH + hh) * SEQ + n0 + n) * HD + (o0 >> 2);
            #pragma unroll
            for (int j = 0; j < 4; j++) {
                *(uint4*)(Ch + dst + 8*j) = *(uint4*)(oh + 8*j);
                *(uint4*)(Cl + dst + 8*j) = *(uint4*)(ol + 8*j);
            }
        }
    } else if (MODE == 3) {
        #pragma unroll
        for (int r = 0; r < 2; r++) {
            const int task = tid + 256*r;
            const int n = task >> 2, hh = task & 3;
            u16 oh[32];
            #pragma unroll
            for (int d = 0; d < 32; d++)
                oh[d] = __half_as_ushort(__float2half_rn(Osm[(4*d + hh)*136 + n] + biasSm[4*d + hh]));
            size_t dst = ((size_t)(b*NH + hh) * SEQ + n0 + n) * HD + (o0 >> 2);
            #pragma unroll
            for (int j = 0; j < 4; j++)
                *(uint4*)(Ch + dst + 8*j) = *(uint4*)(oh + 8*j);
        }
    } else {
        const int o = tid >> 1, mh = (tid & 1) * 64;
        const int chn = o0 + o;
        const int d = chn >> 2, hh = chn & 3;
        const float bi = biasSm[o];
        const float* src = Osm + o*136 + mh;
        u16 xh[64];
        #pragma unroll
        for (int j = 0; j < 64; j++)
            xh[j] = __half_as_ushort(__float2half_rn(src[j] + bi));
        size_t dst = ((size_t)(b*NH + hh) * HD + d) * SEQ + n0 + mh;
        #pragma unroll
        for (int j = 0; j < 8; j++)
            *(uint4*)(Ch + dst + 8*j) = *(uint4*)(xh + 8*j);
    }
}

// ---------------------------------------------------------------------------
// Fused flash attention (R9 best, unchanged): fp16, Q 2-term (pre-scaled),
// K/V/P single-term, ls via all-ones MMA. Double-buffered cp.async. 2 CTAs/SM.
// 256 threads = 8 warps x 16 q-rows. Grid (SEQ/128, BH). smem 106KB.
// ---------------------------------------------------------------------------
#define KPITCH 144
#define VPITCH 272
#define STG 35840            // K (18432) + V (17408) per stage
#define QOFF 71680           // Q hi at QOFF, Q lo at QOFF+18432
#define FLASH_SMEM 108544

__global__ __launch_bounds__(256, 2)
void flash_kernel(const u16* __restrict__ qh, const u16* __restrict__ ql,
                  const u16* __restrict__ kh, const u16* __restrict__ vh,
                  float* __restrict__ X) {
    extern __shared__ __align__(16) char sm[];
    const uint32_t sbase = (uint32_t)__cvta_generic_to_shared(sm);
    const int n0 = blockIdx.x * 128;
    const int bh = blockIdx.y;
    const int b = bh >> 2, h = bh & 3;
    const int t = threadIdx.x;
    const int w = t >> 5, l = t & 31;
    const int g = l >> 2, tt = l & 3;
    const uint32_t ONES = 0x3C003C00u;

    const int km = t >> 1, khalf = (t & 1) * 32;
    const int vd = t >> 2, vm0 = (t & 3) * 32;
    const uint32_t kso = (uint32_t)(km * KPITCH + khalf * 2);
    const uint32_t vso = (uint32_t)(vd * VPITCH + vm0 * 2);
    const u16* kg = kh + ((size_t)bh*SEQ + km) * HD + khalf;
    const u16* vg = vh + ((size_t)bh*HD + vd) * SEQ + vm0;

    const uint32_t kfb = (uint32_t)((l & 7) * KPITCH + 16 * (l >> 3));
    const uint32_t vfb = (uint32_t)(((l & 7) + 8*(l >> 4)) * VPITCH + 16 * ((l >> 3) & 1));

    {
        const u16* qgh = qh + ((size_t)bh*SEQ + n0 + km) * HD + khalf;
        const u16* qgl = ql + ((size_t)bh*SEQ + n0 + km) * HD + khalf;
        #pragma unroll
        for (int u = 0; u < 4; u++) {
            cp16(sbase + QOFF + kso + 16*u,         qgh + 8*u);
            cp16(sbase + QOFF + 18432 + kso + 16*u, qgl + 8*u);
        }
        CP_COMMIT();
        #pragma unroll
        for (int u = 0; u < 4; u++) {
            cp16(sbase + kso + 16*u,         kg + 8*u);
            cp16(sbase + 18432 + vso + 16*u, vg + 8*u);
        }
        CP_COMMIT();
        #pragma unroll
        for (int u = 0; u < 4; u++) {
            cp16(sbase + STG + kso + 16*u,         kg + (size_t)128*HD + 8*u);
            cp16(sbase + STG + 18432 + vso + 16*u, vg + 128 + 8*u);
        }
        CP_COMMIT();
    }
    CP_WAIT(2);
    __syncthreads();
    uint32_t qa_h[4][4], qa_l[4][4];
    {
        const char* QH = sm + QOFF;
        const char* QL = sm + QOFF + 18432;
        const int r0 = (16*w + g) * KPITCH;
        #pragma unroll
        for (int j = 0; j < 4; j++) {
            const int c = (16*j + 2*tt) * 2;
            qa_h[j][0] = *(const uint32_t*)(QH + r0 + c);
            qa_h[j][1] = *(const uint32_t*)(QH + r0 + 8*KPITCH + c);
            qa_h[j][2] = *(const uint32_t*)(QH + r0 + c + 16);
            qa_h[j][3] = *(const uint32_t*)(QH + r0 + 8*KPITCH + c + 16);
            qa_l[j][0] = *(const uint32_t*)(QL + r0 + c);
            qa_l[j][1] = *(const uint32_t*)(QL + r0 + 8*KPITCH + c);
            qa_l[j][2] = *(const uint32_t*)(QL + r0 + c + 16);
            qa_l[j][3] = *(const uint32_t*)(QL + r0 + 8*KPITCH + c + 16);
        }
    }

    float O[8][4];
    #pragma unroll
    for (int i = 0; i < 8; i++) { O[i][0]=0.f; O[i][1]=0.f; O[i][2]=0.f; O[i][3]=0.f; }
    float lsacc[4] = {0.f, 0.f, 0.f, 0.f};
    uint32_t phi[8][2];

    for (int it = 0; it < 16; it++) {
        if (it < 15) { CP_WAIT(1); } else { CP_WAIT(0); }
        __syncthreads();
        const uint32_t kb = sbase + (it & 1) * STG + kfb;
        const uint32_t vb = sbase + (it & 1) * STG + 18432 + vfb;

        #pragma unroll
        for (int half = 0; half < 2; half++) {
            #pragma unroll
            for (int mc = 0; mc < 8; mc++) {
                float sa[4] = {0.f,0.f,0.f,0.f};
                float sb[4] = {0.f,0.f,0.f,0.f};
                const uint32_t rbase = (uint32_t)((64*half + 8*mc) * KPITCH);
                uint32_t bh_[8];
                ldsm4(kb + rbase,      bh_[0], bh_[1], bh_[2], bh_[3]);
                ldsm4(kb + rbase + 64, bh_[4], bh_[5], bh_[6], bh_[7]);
                #pragma unroll
                for (int j = 0; j < 4; j++) {
                    mma16816h(sa, qa_h[j], bh_[2*j], bh_[2*j+1]);
                    mma16816h(sb, qa_l[j], bh_[2*j], bh_[2*j+1]);
                }
                float p0 = ex2f(sa[0] + sb[0]);
                float p1 = ex2f(sa[1] + sb[1]);
                float p2 = ex2f(sa[2] + sb[2]);
                float p3 = ex2f(sa[3] + sb[3]);
                phi[mc][0] = packh2(p0, p1);
                phi[mc][1] = packh2(p2, p3);
            }
            #pragma unroll
            for (int jj = 0; jj < 4; jj++) {
                uint32_t ah[4] = { phi[2*jj][0], phi[2*jj][1], phi[2*jj+1][0], phi[2*jj+1][1] };
                mma16816h(lsacc, ah, ONES, ONES);
                const uint32_t vcol = (uint32_t)(128*half + 32*jj);
                #pragma unroll
                for (int dcp = 0; dcp < 4; dcp++) {
                    uint32_t h0,h1,h2,h3;
                    ldsm4(vb + dcp*(16*VPITCH) + vcol, h0, h1, h2, h3);
                    mma16816h(O[2*dcp],   ah, h0, h1);
                    mma16816h(O[2*dcp+1], ah, h2, h3);
                }
            }
        }
        __syncthreads();
        if (it < 14) {
            const u16* pk = kg + (size_t)(it + 2) * 128 * HD;
            const u16* pv = vg + (size_t)(it + 2) * 128;
            const uint32_t dk = sbase + (it & 1) * STG + kso;
            const uint32_t dv = sbase + (it & 1) * STG + 18432 + vso;
            #pragma unroll
            for (int u = 0; u < 4; u++) {
                cp16(dk + 16*u, pk + 8*u);
                cp16(dv + 16*u, pv + 8*u);
            }
            CP_COMMIT();
        }
    }

    const float i0 = 1.f / lsacc[0], i1 = 1.f / lsacc[2];
    #pragma unroll
    for (int dc = 0; dc < 8; dc++) {
        const int d0 = 8*dc + 2*tt;
        float* xp = X + ((size_t)b*DM + 4*d0 + h) * SEQ + n0 + 16*w;
        xp[g]             = O[dc][0] * i0;
        xp[4*SEQ + g]     = O[dc][1] * i0;
        xp[g + 8]         = O[dc][2] * i1;
        xp[4*SEQ + g + 8] = O[dc][3] * i1;
    }
}

// ---------------------------------------------------------------------------
extern "C" void kernel_launch(void* const* d_in, const int* in_sizes, int n_in,
                              void* d_out, int out_size) {
    const float* query = (const float*)d_in[0];
    const float* key   = (const float*)d_in[1];
    const float* value = (const float*)d_in[2];
    const float* Wq = (const float*)d_in[3];
    const float* bq = (const float*)d_in[4];
    const float* Wk = (const float*)d_in[5];
    const float* bk = (const float*)d_in[6];
    const float* Wv = (const float*)d_in[7];
    const float* bv = (const float*)d_in[8];
    const float* Wm = (const float*)d_in[9];
    const float* bm = (const float*)d_in[10];

    u16 *qh, *ql, *kh, *vh, *wh, *wl;
    float *x;
    cudaGetSymbolAddress((void**)&qh, g_qh);
    cudaGetSymbolAddress((void**)&ql, g_ql);
    cudaGetSymbolAddress((void**)&kh, g_kh);
    cudaGetSymbolAddress((void**)&vh, g_vh);
    cudaGetSymbolAddress((void**)&wh, g_wh);
    cudaGetSymbolAddress((void**)&wl, g_wl);
    cudaGetSymbolAddress((void**)&x,  g_x);

    cudaFuncSetAttribute(flash_kernel, cudaFuncAttributeMaxDynamicSharedMemorySize, FLASH_SMEM);
    cudaFuncSetAttribute(proj_tc<0>, cudaFuncAttributeMaxDynamicSharedMemorySize, PSM_BYTES);
    cudaFuncSetAttribute(proj_tc<1>, cudaFuncAttributeMaxDynamicSharedMemorySize, PSM_BYTES);
    cudaFuncSetAttribute(proj_tc<2>, cudaFuncAttributeMaxDynamicSharedMemorySize, PSM_BYTES);
    cudaFuncSetAttribute(proj_tc<3>, cudaFuncAttributeMaxDynamicSharedMemorySize, PSM_BYTES);

    wsplit_kernel<<<dim3(32, 4), 256>>>(Wq, Wk, Wv, Wm, wh, wl);

    dim3 pjGrid(SEQ/128, DM/128, BATCH);
    proj_tc<1><<<pjGrid, 256, PSM_BYTES>>>(wh,           wl,           bq, query, nullptr, qh, ql);
    proj_tc<3><<<pjGrid, 256, PSM_BYTES>>>(wh + DM*DM,   wl + DM*DM,   bk, key,   nullptr, kh, nullptr);
    proj_tc<2><<<pjGrid, 256, PSM_BYTES>>>(wh + 2*DM*DM, wl + 2*DM*DM, bv, value, nullptr, vh, nullptr);

    flash_kernel<<<dim3(SEQ/128, BH), 256, FLASH_SMEM>>>(qh, ql, kh, vh, x);

    proj_tc<0><<<pjGrid, 256, PSM_BYTES>>>(wh + 3*DM*DM, wl + 3*DM*DM, bm, x, (float*)d_out, nullptr, nullptr);
}